// round 3
// baseline (speedup 1.0000x reference)
#include <cuda_runtime.h>
#include <math.h>
#include <stdint.h>

#define NN 8192
#define T 64
#define STR 65                      // padded row stride (floats) — conflict-free both orientations
#define NT (NN / T)                 // 128
#define NPAIRS (NT * (NT + 1) / 2)  // 8256 upper-tri tile pairs
#define PPB 4                       // pairs per block (pipelined)
#define NBLK (NPAIRS / PPB)         // 2064
#define THREADS 512
#define TILE_FLOATS (T * STR)       // 4160
#define PAIR_FLOATS (2 * TILE_FLOATS)
#define DYN_SMEM (2 * PAIR_FLOATS * 4)  // two ping-pong pair buffers = 66560 B

__device__ float g_part[NT][NN];    // deterministic per-slot partial rowsums
__device__ float g_d[NN];

// ---------------------------------------------------------------------------
// helpers
// ---------------------------------------------------------------------------
__device__ __forceinline__ void tri_decode(int t, int& bi, int& bj) {
    float a = 2.0f * NT + 1.0f;
    int b = (int)(0.5f * (a - sqrtf(a * a - 8.0f * (float)t)));
    if (b < 0) b = 0;
    if (b > NT - 1) b = NT - 1;
    while (b > 0 && (b * NT - b * (b - 1) / 2) > t) b--;
    while (((b + 1) * NT - (b + 1) * b / 2) <= t) b++;
    bi = b;
    bj = b + (t - (b * NT - b * (b - 1) / 2));
}

__device__ __forceinline__ void cp_async4(uint32_t dst, const float* src) {
    asm volatile("cp.async.ca.shared.global [%0], [%1], 4;" :: "r"(dst), "l"(src));
}
__device__ __forceinline__ void cp_commit() {
    asm volatile("cp.async.commit_group;" ::: "memory");
}
template <int N>
__device__ __forceinline__ void cp_wait() {
    asm volatile("cp.async.wait_group %0;" :: "n"(N) : "memory");
}

// Issue async loads for one tile pair into buffer `buf` (u32 smem address).
// Thread layout: col = tid&63 (fast, coalesced), rb = tid>>6; 8 rows each.
__device__ __forceinline__ void issue_pair(uint32_t buf, const float* __restrict__ adj,
                                           int bi, int bj, int tid) {
    int col = tid & 63;
    int rb = tid >> 6;
    const float* srcA = adj + (size_t)(bi * T) * NN + (size_t)(bj * T);
    #pragma unroll
    for (int i = 0; i < 8; i++) {
        int row = rb * 8 + i;
        cp_async4(buf + (uint32_t)(row * STR + col) * 4u, srcA + (size_t)row * NN + col);
    }
    if (bi != bj) {
        const float* srcB = adj + (size_t)(bj * T) * NN + (size_t)(bi * T);
        uint32_t bufB = buf + (uint32_t)TILE_FLOATS * 4u;
        #pragma unroll
        for (int i = 0; i < 8; i++) {
            int row = rb * 8 + i;
            cp_async4(bufB + (uint32_t)(row * STR + col) * 4u, srcB + (size_t)row * NN + col);
        }
    }
    cp_commit();
}

// ---------------------------------------------------------------------------
// Pass 1: rowsum partials, 4 pipelined tile pairs per block.
// ---------------------------------------------------------------------------
__global__ __launch_bounds__(THREADS, 3) void pass1_kernel(const float* __restrict__ adj) {
    extern __shared__ float sm[];
    __shared__ float rpart[8][T];
    __shared__ float cpart[8][T];

    int tid = threadIdx.x;
    uint32_t smbase = (uint32_t)__cvta_generic_to_shared(sm);
    int pair0 = blockIdx.x * PPB;

    int bis[PPB], bjs[PPB];
    #pragma unroll
    for (int p = 0; p < PPB; p++) tri_decode(pair0 + p, bis[p], bjs[p]);

    // prologue: two pairs in flight
    issue_pair(smbase, adj, bis[0], bjs[0], tid);
    issue_pair(smbase + (uint32_t)PAIR_FLOATS * 4u, adj, bis[1], bjs[1], tid);

    int c = tid & 63;
    int q = tid >> 6;

    #pragma unroll
    for (int p = 0; p < PPB; p++) {
        const float* s1 = sm + (p & 1) * PAIR_FLOATS;
        const float* s2 = s1 + TILE_FLOATS;
        int bi = bis[p], bj = bjs[p];
        bool diag = (bi == bj);

        if (p == PPB - 1) cp_wait<0>(); else cp_wait<1>();
        __syncthreads();

        if (diag) {
            float racc = 0.0f;
            #pragma unroll
            for (int j = 0; j < 8; j++) {
                int cc = q * 8 + j;
                racc += fmaxf(s1[c * STR + cc], s1[cc * STR + c]);
            }
            rpart[q][c] = racc;
        } else {
            float racc = 0.0f, cacc = 0.0f;
            #pragma unroll
            for (int j = 0; j < 8; j++) {
                int cc = q * 8 + j;
                racc += fmaxf(s1[c * STR + cc], s2[cc * STR + c]);
                cacc += fmaxf(s1[cc * STR + c], s2[c * STR + cc]);
            }
            rpart[q][c] = racc;
            cpart[q][c] = cacc;
        }
        __syncthreads();

        if (tid < T) {
            float s = 0.0f;
            #pragma unroll
            for (int k = 0; k < 8; k++) s += rpart[k][tid];
            g_part[bj][bi * T + tid] = s;
        } else if (!diag && tid < 2 * T) {
            int u = tid - T;
            float s = 0.0f;
            #pragma unroll
            for (int k = 0; k < 8; k++) s += cpart[k][u];
            g_part[bi][bj * T + u] = s;
        }

        if (p + 2 < PPB)
            issue_pair(smbase + (uint32_t)((p & 1) * PAIR_FLOATS) * 4u,
                       adj, bis[p + 2], bjs[p + 2], tid);
    }
}

// ---------------------------------------------------------------------------
// d[i] = (1 + sum_k part[k][i])^-1/2   (rowsum >= 1, never inf)
// ---------------------------------------------------------------------------
__global__ __launch_bounds__(256) void reduce_d_kernel() {
    int i = blockIdx.x * blockDim.x + threadIdx.x;
    float s = 1.0f;  // self-loop
    #pragma unroll 8
    for (int k = 0; k < NT; k++) s += g_part[k][i];
    g_d[i] = rsqrtf(s);
}

// ---------------------------------------------------------------------------
// Pass 2: out[i][j] = d[i]*d[j]*(max(adj[i][j], adj[j][i]) + (i==j))
// Same 4-pair pipeline; d read via broadcast LDG (L1/L2-resident, 32 KB).
// ---------------------------------------------------------------------------
__global__ __launch_bounds__(THREADS, 3) void pass2_kernel(const float* __restrict__ adj,
                                                           float* __restrict__ out) {
    extern __shared__ float sm[];
    int tid = threadIdx.x;
    uint32_t smbase = (uint32_t)__cvta_generic_to_shared(sm);
    int pair0 = blockIdx.x * PPB;

    int bis[PPB], bjs[PPB];
    #pragma unroll
    for (int p = 0; p < PPB; p++) tri_decode(pair0 + p, bis[p], bjs[p]);

    issue_pair(smbase, adj, bis[0], bjs[0], tid);
    issue_pair(smbase + (uint32_t)PAIR_FLOATS * 4u, adj, bis[1], bjs[1], tid);

    int c = tid & 63;
    int q = tid >> 6;

    #pragma unroll
    for (int p = 0; p < PPB; p++) {
        const float* s1 = sm + (p & 1) * PAIR_FLOATS;
        const float* s2 = s1 + TILE_FLOATS;
        int bi = bis[p], bj = bjs[p];
        bool diag = (bi == bj);

        if (p == PPB - 1) cp_wait<0>(); else cp_wait<1>();
        __syncthreads();

        if (diag) {
            float dc = g_d[bi * T + c];
            float* po = out + (size_t)(bi * T) * NN + (size_t)(bi * T);
            #pragma unroll
            for (int j = 0; j < 8; j++) {
                int r = q * 8 + j;
                float dr = g_d[bi * T + r];
                float v = fmaxf(s1[r * STR + c], s1[c * STR + r]) + ((r == c) ? 1.0f : 0.0f);
                po[(size_t)r * NN + c] = dr * dc * v;
            }
        } else {
            float dcB = g_d[bj * T + c];
            float dcA = g_d[bi * T + c];
            float* po1 = out + (size_t)(bi * T) * NN + (size_t)(bj * T);
            float* po2 = out + (size_t)(bj * T) * NN + (size_t)(bi * T);
            #pragma unroll
            for (int j = 0; j < 8; j++) {
                int r = q * 8 + j;
                float drA = g_d[bi * T + r];
                float v1 = fmaxf(s1[r * STR + c], s2[c * STR + r]);
                po1[(size_t)r * NN + c] = drA * dcB * v1;
                float drB = g_d[bj * T + r];
                float v2 = fmaxf(s2[r * STR + c], s1[c * STR + r]);
                po2[(size_t)r * NN + c] = drB * dcA * v2;
            }
        }
        __syncthreads();

        if (p + 2 < PPB)
            issue_pair(smbase + (uint32_t)((p & 1) * PAIR_FLOATS) * 4u,
                       adj, bis[p + 2], bjs[p + 2], tid);
    }
}

extern "C" void kernel_launch(void* const* d_in, const int* in_sizes, int n_in,
                              void* d_out, int out_size) {
    const float* adj = (const float*)d_in[0];
    float* out = (float*)d_out;
    (void)in_sizes; (void)n_in; (void)out_size;

    cudaFuncSetAttribute(pass1_kernel, cudaFuncAttributeMaxDynamicSharedMemorySize, DYN_SMEM);
    cudaFuncSetAttribute(pass2_kernel, cudaFuncAttributeMaxDynamicSharedMemorySize, DYN_SMEM);

    pass1_kernel<<<NBLK, THREADS, DYN_SMEM>>>(adj);
    reduce_d_kernel<<<NN / 256, 256>>>();
    pass2_kernel<<<NBLK, THREADS, DYN_SMEM>>>(adj, out);
}

// round 4
// speedup vs baseline: 1.3329x; 1.3329x over previous
#include <cuda_runtime.h>
#include <math.h>
#include <stdint.h>

#define NN 8192
#define T 64
#define NT (NN / T)                 // 128
#define NPAIRS (NT * (NT + 1) / 2)  // 8256 upper-tri tile pairs

// 16B-granular XOR swizzle: physical chunk = logical_chunk ^ ((row>>2)&7).
// Stride 64 floats (256B rows, 16B aligned). Conflict-free for:
//   - cp.async.16 stores (16 lanes, one row, chunks 0..15^const)
//   - row-patch LDS.128 (fixed row, chunk c4^(g&7))
//   - transposed-patch LDS.128 (rows 4*c4+e, chunk g^(c4&7))
#define SWZ(r) (((r) >> 2) & 7)

__device__ float g_part[NT][NN];    // deterministic per-slot partial rowsums (4 MB)
__device__ float g_d[NN];

// ---------------------------------------------------------------------------
__device__ __forceinline__ void tri_decode(int t, int& bi, int& bj) {
    float a = 2.0f * NT + 1.0f;
    int b = (int)(0.5f * (a - sqrtf(a * a - 8.0f * (float)t)));
    if (b < 0) b = 0;
    if (b > NT - 1) b = NT - 1;
    while (b > 0 && (b * NT - b * (b - 1) / 2) > t) b--;
    while (((b + 1) * NT - (b + 1) * b / 2) <= t) b++;
    bi = b;
    bj = b + (t - (b * NT - b * (b - 1) / 2));
}

__device__ __forceinline__ void cp_async16(uint32_t dst, const float* src) {
    asm volatile("cp.async.cg.shared.global [%0], [%1], 16;" :: "r"(dst), "l"(src));
}
__device__ __forceinline__ void cp_commit() {
    asm volatile("cp.async.commit_group;" ::: "memory");
}
__device__ __forceinline__ void cp_wait0() {
    asm volatile("cp.async.wait_group 0;" ::: "memory");
}

// Issue one 64x64 tile load: thread (g = tid>>4, c4 = tid&15) loads 4 rows.
__device__ __forceinline__ void load_tile(uint32_t sbase, const float* __restrict__ src,
                                          int g, int c4) {
    #pragma unroll
    for (int k = 0; k < 4; k++) {
        int row = g + 16 * k;
        uint32_t dst = sbase + (uint32_t)((row * 64 + 4 * (c4 ^ SWZ(row))) * 4);
        cp_async16(dst, src + (size_t)row * NN + 4 * c4);
    }
}

// ---------------------------------------------------------------------------
// Pass 1: rowsum partials. One block per tile pair; each thread owns a 4x4
// patch, computes each max once, accumulates row+col partials in registers.
// ---------------------------------------------------------------------------
__global__ __launch_bounds__(256) void pass1_kernel(const float* __restrict__ adj) {
    __shared__ float s1[T * T];
    __shared__ float s2[T * T];
    __shared__ float rbuf[16][68];   // rbuf[c4][row]  (pad 68: conflict-free)
    __shared__ float cbuf[16][68];   // cbuf[g][col]

    int bi, bj;
    tri_decode(blockIdx.x, bi, bj);
    int tid = threadIdx.x;
    int c4 = tid & 15, g = tid >> 4;
    bool diag = (bi == bj);

    uint32_t s1a = (uint32_t)__cvta_generic_to_shared(s1);
    uint32_t s2a = (uint32_t)__cvta_generic_to_shared(s2);

    load_tile(s1a, adj + (size_t)(bi * T) * NN + (size_t)(bj * T), g, c4);
    if (!diag)
        load_tile(s2a, adj + (size_t)(bj * T) * NN + (size_t)(bi * T), g, c4);
    cp_commit();
    cp_wait0();
    __syncthreads();

    int ca = c4 ^ (g & 7);      // s1 row-patch physical chunk
    int gb = g ^ (c4 & 7);      // transposed-patch physical chunk

    float a[4][4], b[4][4];
    #pragma unroll
    for (int i = 0; i < 4; i++)
        *(float4*)a[i] = *(const float4*)(s1 + (4 * g + i) * 64 + 4 * ca);
    const float* sB = diag ? s1 : s2;
    #pragma unroll
    for (int e = 0; e < 4; e++)
        *(float4*)b[e] = *(const float4*)(sB + (4 * c4 + e) * 64 + 4 * gb);

    float rs[4] = {0, 0, 0, 0}, cs[4] = {0, 0, 0, 0};
    #pragma unroll
    for (int i = 0; i < 4; i++)
        #pragma unroll
        for (int e = 0; e < 4; e++) {
            float v = fmaxf(a[i][e], b[e][i]);
            rs[i] += v;
            cs[e] += v;
        }

    *(float4*)&rbuf[c4][4 * g] = make_float4(rs[0], rs[1], rs[2], rs[3]);
    *(float4*)&cbuf[g][4 * c4] = make_float4(cs[0], cs[1], cs[2], cs[3]);
    __syncthreads();

    if (tid < T) {
        float s = 0.0f;
        #pragma unroll
        for (int k = 0; k < 16; k++) s += rbuf[k][tid];
        g_part[bj][bi * T + tid] = s;            // rows of block bi
    } else if (!diag && tid < 2 * T) {
        int u = tid - T;
        float s = 0.0f;
        #pragma unroll
        for (int k = 0; k < 16; k++) s += cbuf[k][u];
        g_part[bi][bj * T + u] = s;              // rows of block bj
    }
}

// ---------------------------------------------------------------------------
// d[i] = (1 + sum_k part[k][i])^-1/2   (rowsum >= 1, never inf)
// ---------------------------------------------------------------------------
__global__ __launch_bounds__(256) void reduce_d_kernel() {
    int i = blockIdx.x * blockDim.x + threadIdx.x;
    float s = 1.0f;  // self-loop
    #pragma unroll 8
    for (int k = 0; k < NT; k++) s += g_part[k][i];
    g_d[i] = rsqrtf(s);
}

// ---------------------------------------------------------------------------
// Pass 2: out = d[i]*d[j]*(m + I). Same 4x4 patch scheme; both output tiles
// written with coalesced STG.128 (transposed tile staged through s2's buffer).
// ---------------------------------------------------------------------------
__global__ __launch_bounds__(256) void pass2_kernel(const float* __restrict__ adj,
                                                    float* __restrict__ out) {
    __shared__ float s1[T * T];
    __shared__ float s2[T * T];      // also reused as transposed-output staging
    __shared__ float sd[2 * T];

    int bi, bj;
    tri_decode(blockIdx.x, bi, bj);
    int tid = threadIdx.x;
    int c4 = tid & 15, g = tid >> 4;
    bool diag = (bi == bj);

    uint32_t s1a = (uint32_t)__cvta_generic_to_shared(s1);
    uint32_t s2a = (uint32_t)__cvta_generic_to_shared(s2);

    load_tile(s1a, adj + (size_t)(bi * T) * NN + (size_t)(bj * T), g, c4);
    if (!diag)
        load_tile(s2a, adj + (size_t)(bj * T) * NN + (size_t)(bi * T), g, c4);
    if (tid < T) sd[tid] = g_d[bi * T + tid];
    else if (tid < 2 * T) sd[tid] = g_d[bj * T + (tid - T)];
    cp_commit();
    cp_wait0();
    __syncthreads();

    int ca = c4 ^ (g & 7);
    int gb = g ^ (c4 & 7);

    float a[4][4], b[4][4];
    #pragma unroll
    for (int i = 0; i < 4; i++)
        *(float4*)a[i] = *(const float4*)(s1 + (4 * g + i) * 64 + 4 * ca);
    const float* sB = diag ? s1 : s2;
    #pragma unroll
    for (int e = 0; e < 4; e++)
        *(float4*)b[e] = *(const float4*)(sB + (4 * c4 + e) * 64 + 4 * gb);

    float dA[4], dB[4];
    #pragma unroll
    for (int i = 0; i < 4; i++) dA[i] = sd[4 * g + i];
    #pragma unroll
    for (int e = 0; e < 4; e++) dB[e] = sd[T + 4 * c4 + e];

    // w[i][e] = d_row * d_col * (max + diag)
    float w[4][4];
    #pragma unroll
    for (int i = 0; i < 4; i++)
        #pragma unroll
        for (int e = 0; e < 4; e++) {
            float v = fmaxf(a[i][e], b[e][i]);
            if (diag && g == c4 && i == e) v += 1.0f;
            w[i][e] = dA[i] * dB[e] * v;
        }

    // Output tile 1 (rows of block bi): coalesced STG.128
    float* po1 = out + (size_t)(bi * T) * NN + (size_t)(bj * T);
    #pragma unroll
    for (int i = 0; i < 4; i++)
        *(float4*)(po1 + (size_t)(4 * g + i) * NN + 4 * c4) = *(float4*)w[i];

    if (!diag) {
        // Stage transposed tile into s2 (swizzled, conflict-free), then write
        // coalesced. w is symmetric-pair value: out2[r'][c'] = w[c'][r'].
        __syncthreads();   // all reads of s2 complete (w is in registers)
        #pragma unroll
        for (int e = 0; e < 4; e++)
            *(float4*)(s2 + (4 * c4 + e) * 64 + 4 * gb) =
                make_float4(w[0][e], w[1][e], w[2][e], w[3][e]);
        __syncthreads();

        float* po2 = out + (size_t)(bj * T) * NN + (size_t)(bi * T);
        #pragma unroll
        for (int i = 0; i < 4; i++) {
            float4 o = *(const float4*)(s2 + (4 * g + i) * 64 + 4 * ca);
            *(float4*)(po2 + (size_t)(4 * g + i) * NN + 4 * c4) = o;
        }
    }
}

extern "C" void kernel_launch(void* const* d_in, const int* in_sizes, int n_in,
                              void* d_out, int out_size) {
    const float* adj = (const float*)d_in[0];
    float* out = (float*)d_out;
    (void)in_sizes; (void)n_in; (void)out_size;

    pass1_kernel<<<NPAIRS, 256>>>(adj);
    reduce_d_kernel<<<NN / 256, 256>>>();
    pass2_kernel<<<NPAIRS, 256>>>(adj, out);
}